// round 13
// baseline (speedup 1.0000x reference)
#include <cuda_runtime.h>
#include <cuda_fp16.h>
#include <cstdint>

// Problem constants
#define T_  512
#define B_  64
#define NI_ 512
#define NH_ 1024
#define NG_ 4096          // 4*NH
#define TB_ (T_*B_)       // 32768
#define NCTA 128

// ---------------------------------------------------------------------------
// Device scratch (static — no allocations anywhere)
// ---------------------------------------------------------------------------
__device__ __align__(16) __half g_x16[TB_ * NI_];              //  32 MB fp16 input
__device__ __align__(16) __half g_wih[2][NG_ * NI_];           // permuted W_ih [p][k]
__device__ __align__(16) __half g_whh[2][NG_ * NH_];           // permuted W_hh [p][k]
__device__ __align__(16) float  g_bias[2][NG_];                // b_ih+b_hh, permuted
__device__ __align__(16) __half g_xw[2][(size_t)TB_ * NG_];    // 536 MB x@W_ih^T + biases
__device__ __align__(16) __half g_h16[2][B_ * NH_];            // h ping-pong (fp16)
__device__ __align__(128) unsigned g_flag[8 * 32];             // per-chunk producer flags

// ---------------------------------------------------------------------------
// PTX helpers
// ---------------------------------------------------------------------------
__device__ __forceinline__ void cp16(void* dst, const void* src) {
    uint32_t d = (uint32_t)__cvta_generic_to_shared(dst);
    asm volatile("cp.async.cg.shared.global [%0], [%1], 16;\n" :: "r"(d), "l"(src));
}
__device__ __forceinline__ void cp_commit() {
    asm volatile("cp.async.commit_group;\n");
}
__device__ __forceinline__ void ldsm4(uint32_t* r, const void* p) {
    uint32_t a = (uint32_t)__cvta_generic_to_shared(p);
    asm volatile("ldmatrix.sync.aligned.m8n8.x4.shared.b16 {%0,%1,%2,%3}, [%4];\n"
                 : "=r"(r[0]), "=r"(r[1]), "=r"(r[2]), "=r"(r[3]) : "r"(a));
}
__device__ __forceinline__ void mma16816(float* c, const uint32_t* a, uint32_t b0, uint32_t b1) {
    asm volatile(
        "mma.sync.aligned.m16n8k16.row.col.f32.f16.f16.f32 "
        "{%0,%1,%2,%3},{%4,%5,%6,%7},{%8,%9},{%0,%1,%2,%3};\n"
        : "+f"(c[0]), "+f"(c[1]), "+f"(c[2]), "+f"(c[3])
        : "r"(a[0]), "r"(a[1]), "r"(a[2]), "r"(a[3]), "r"(b0), "r"(b1));
}
__device__ __forceinline__ unsigned ld_acq(const unsigned* p) {
    unsigned v;
    asm volatile("ld.acquire.gpu.u32 %0, [%1];" : "=r"(v) : "l"(p) : "memory");
    return v;
}
__device__ __forceinline__ void red_rel_add(unsigned* p, unsigned v) {
    asm volatile("red.release.gpu.add.u32 [%0], %1;" :: "l"(p), "r"(v) : "memory");
}
__device__ __forceinline__ float sigmoidf_(float x) {
    return 1.f / (1.f + __expf(-x));
}
__device__ __forceinline__ float tanhf_(float x) {
    x = fminf(fmaxf(x, -15.f), 15.f);
    float e = __expf(2.f * x);
    return (e - 1.f) / (e + 1.f);
}

// ---------------------------------------------------------------------------
// Prep kernels
// ---------------------------------------------------------------------------
__global__ void k_convert_x(const float* __restrict__ x) {
    int i = (blockIdx.x * blockDim.x + threadIdx.x) * 4;
    float4 v = *reinterpret_cast<const float4*>(x + i);
    *reinterpret_cast<__half2*>(g_x16 + i)     = __floats2half2_rn(v.x, v.y);
    *reinterpret_cast<__half2*>(g_x16 + i + 2) = __floats2half2_rn(v.z, v.w);
}

// Permutation: p = 4*j + g  <->  original row r = g*NH + j   (gate order i,f,g,o)
__global__ void k_prep(const float* __restrict__ wih_e, const float* __restrict__ whh_e,
                       const float* __restrict__ bih_e, const float* __restrict__ bhh_e,
                       const float* __restrict__ wih_d, const float* __restrict__ whh_d,
                       const float* __restrict__ bih_d, const float* __restrict__ bhh_d) {
    const long total = 2L * NG_ * NH_;
    for (long i = (long)blockIdx.x * blockDim.x + threadIdx.x; i < total;
         i += (long)gridDim.x * blockDim.x) {
        int  e   = (i >= (long)NG_ * NH_);
        long rem = i - (long)e * NG_ * NH_;
        int  p   = (int)(rem >> 10);
        int  k   = (int)(rem & (NH_ - 1));
        int  r   = ((p & 3) << 10) + (p >> 2);        // g*1024 + j
        const float* whh = e ? whh_d : whh_e;
        g_whh[e][p * NH_ + k] = __float2half(whh[r * NH_ + k]);
        if (k < NI_) {
            const float* wih = e ? wih_d : wih_e;
            g_wih[e][p * NI_ + k] = __float2half(wih[r * NI_ + k]);
        }
        if (k == 0) {
            g_bias[e][p] = e ? (bih_d[r] + bhh_d[r]) : (bih_e[r] + bhh_e[r]);
        }
    }
}

__global__ void k_init() {
    int i = blockIdx.x * blockDim.x + threadIdx.x;
    if (i < B_ * NH_) {
        g_h16[0][i] = __float2half(0.f);
    }
    if (i < 8 * 32) {
        g_flag[i] = 0u;
    }
}

// ---------------------------------------------------------------------------
// Input projection GEMM: g_xw[e][tb][p] = x16[tb]·Wih[p] + bias[p]   (fp16 out)
// Tiles: M64 x N64, K=512 (BK=64, 8 iters). blockIdx.z = enc/dec.
// ---------------------------------------------------------------------------
__global__ void __launch_bounds__(128) k_xw_gemm() {
    const int e = blockIdx.z;
    const __half* __restrict__ Bw   = g_wih[e];
    const float*  __restrict__ bias = g_bias[e];
    __half*       __restrict__ outp = g_xw[e];

    __shared__ __align__(16) __half sA[2][64][72];
    __shared__ __align__(16) __half sB[2][64][72];

    int tid = threadIdx.x, warp = tid >> 5, lane = tid & 31;
    int mb = blockIdx.y * 64, nb = blockIdx.x * 64;

    float acc[8][4];
#pragma unroll
    for (int i = 0; i < 8; i++)
#pragma unroll
        for (int j = 0; j < 4; j++) acc[i][j] = 0.f;

#pragma unroll
    for (int c = tid; c < 512; c += 128) {
        int r = c >> 3, o = (c & 7) * 8;
        cp16(&sA[0][r][o], g_x16 + (mb + r) * NI_ + o);
    }
#pragma unroll
    for (int c = tid; c < 512; c += 128) {
        int r = c >> 3, o = (c & 7) * 8;
        cp16(&sB[0][r][o], Bw + (nb + r) * NI_ + o);
    }
    cp_commit();

    for (int kt = 0; kt < 8; kt++) {
        if (kt + 1 < 8) {
            int st = (kt + 1) & 1, k0 = (kt + 1) * 64;
#pragma unroll
            for (int c = tid; c < 512; c += 128) {
                int r = c >> 3, o = (c & 7) * 8;
                cp16(&sA[st][r][o], g_x16 + (mb + r) * NI_ + k0 + o);
            }
#pragma unroll
            for (int c = tid; c < 512; c += 128) {
                int r = c >> 3, o = (c & 7) * 8;
                cp16(&sB[st][r][o], Bw + (nb + r) * NI_ + k0 + o);
            }
            cp_commit();
            asm volatile("cp.async.wait_group 1;\n");
        } else {
            asm volatile("cp.async.wait_group 0;\n");
        }
        __syncthreads();
        int st = kt & 1;
#pragma unroll
        for (int ks = 0; ks < 4; ks++) {
            uint32_t a[4];
            ldsm4(a, &sA[st][warp * 16 + (lane & 15)][ks * 16 + ((lane >> 4) << 3)]);
#pragma unroll
            for (int n2 = 0; n2 < 4; n2++) {
                uint32_t b[4];
                int nr = n2 * 16 + (lane & 7) + ((lane >> 4) << 3);
                int kc = ks * 16 + ((lane >> 3) & 1) * 8;
                ldsm4(b, &sB[st][nr][kc]);
                mma16816(acc[n2 * 2 + 0], a, b[0], b[1]);
                mma16816(acc[n2 * 2 + 1], a, b[2], b[3]);
            }
        }
        __syncthreads();
    }

    int r0 = mb + warp * 16 + (lane >> 2);
#pragma unroll
    for (int nt = 0; nt < 8; nt++) {
        int cg = nb + nt * 8 + ((lane & 3) << 1);
        float b0 = bias[cg], b1 = bias[cg + 1];
        __half2 v0 = __floats2half2_rn(acc[nt][0] + b0, acc[nt][1] + b1);
        __half2 v1 = __floats2half2_rn(acc[nt][2] + b0, acc[nt][3] + b1);
        *reinterpret_cast<__half2*>(outp + (size_t)r0 * NG_ + cg)       = v0;
        *reinterpret_cast<__half2*>(outp + (size_t)(r0 + 8) * NG_ + cg) = v1;
    }
}

// ---------------------------------------------------------------------------
// Persistent step kernel. 128 CTAs x 256 threads (8 warps, split-K), one CTA
// per SM. CTA bx owns permuted gate cols [32bx,32bx+32) = hidden units
// [8bx,8bx+8). h chunk c (cols 128c..128c+127) is produced by CTAs 16c..16c+15.
// Per-chunk producer flags (8, monotonic counters) replace the global barrier:
// a consumer spins on flag[c] >= 16*s right before issuing chunk c's cp.async
// group; chunk order is rotated per-CTA to start with its own group. Producers
// bump their group flag with red.release after storing their h slice.
// SMEM: wsm [32][1032] 66048 | sA [64][1032] 132096 | sxw [64][32] 4096 |
//       gsm0+gsm1 2x[4][16][33] f32 16896 | csm [64][8] f32 2048 = 221184 B
// ---------------------------------------------------------------------------
#define SMEM_PERSIST 221184

__device__ __forceinline__ void issue_chunk(__half* sA, const __half* hin,
                                            int cc, int tid) {
#pragma unroll
    for (int i = tid; i < 1024; i += 256) {
        int r = i >> 4, o = (i & 15) * 8;
        cp16(sA + r * 1032 + cc * 128 + o, hin + r * NH_ + cc * 128 + o);
    }
}

__global__ void __launch_bounds__(256, 1) k_persist(const float* __restrict__ mask,
                                                    float* __restrict__ outp) {
    extern __shared__ __align__(16) unsigned char smem_raw[];
    __half* wsm  = reinterpret_cast<__half*>(smem_raw);       // [32][1032]
    __half* sA   = wsm + 32 * 1032;                           // [64][1032]
    __half* sxw  = sA + 64 * 1032;                            // [64][32]
    float*  gsm0 = reinterpret_cast<float*>(sxw + 64 * 32);   // [4][16][33]
    float*  gsm1 = gsm0 + 4 * 16 * 33;                        // [4][16][33]
    float*  csm  = gsm1 + 4 * 16 * 33;                        // [64][8]

    const int tid  = threadIdx.x, warp = tid >> 5, lane = tid & 31;
    const int mw   = warp & 3;          // M-row group (rows 16*mw..)
    const int kh   = warp >> 2;         // K-half (ks offset kh*64 within chunk)
    const int cta  = blockIdx.x;
    const int c0   = cta * 32;
    const int grp  = cta >> 4;          // h-chunk this CTA produces

    // zero c-state (CTA-local, SMEM-resident)
    for (int i = tid; i < 64 * 8; i += 256) csm[i] = 0.f;

    for (int s = 0; s < 1024; s++) {
        const bool enc = (s < 512);
        const int  t   = enc ? s : s - 512;
        const int  e   = enc ? 0 : 1;
        const __half* __restrict__ hin  = g_h16[s & 1];
        __half*       __restrict__ hout = g_h16[(s + 1) & 1];
        const unsigned tgt = 16u * (unsigned)s;

        // phase start: load this CTA's W_hh slice (enc at s=0, dec at s=512)
        if (s == 0 || s == 512) {
            __syncthreads();   // prior-step mma fully done before overwrite
            const __half* src = g_whh[e] + (size_t)c0 * NH_;
            for (int i = tid; i < 32 * 128; i += 256) {
                int r = i >> 7, ch = i & 127;
                cp16(wsm + r * 1032 + ch * 8, src + r * NH_ + ch * 8);
            }
            cp_commit();
            asm volatile("cp.async.wait_group 0;\n");
            __syncthreads();
        }

        // ---- prologue: issue groups for chunks grp, grp+1 (flag-gated) ----
        if (s > 0 && tid == 0) {
            while (ld_acq(&g_flag[grp * 32]) < tgt) {}
        }
        __syncthreads();
        {
            const __half* xwsrc = g_xw[e] + (size_t)(t * 64) * NG_ + c0;
            int b = tid >> 2, o = (tid & 3) * 8;
            cp16(sxw + b * 32 + o, xwsrc + (size_t)b * NG_ + o);
            issue_chunk(sA, hin, grp, tid);
            cp_commit();
        }
        {
            int cn = (grp + 1) & 7;
            if (s > 0 && tid == 0) {
                while (ld_acq(&g_flag[cn * 32]) < tgt) {}
            }
            __syncthreads();
            issue_chunk(sA, hin, cn, tid);
            cp_commit();
        }

        float acc[4][4];
#pragma unroll
        for (int i = 0; i < 4; i++)
#pragma unroll
            for (int j = 0; j < 4; j++) acc[i][j] = 0.f;

        // per chunk: spin(c+2) -> wait(chunk c landed) -> sync -> issue(c+2) -> mma(c)
#define DO_CHUNK(C, WG)                                                         \
        do {                                                                    \
            const int cc = (grp + (C)) & 7;                                     \
            if ((C) + 2 < 8) {                                                  \
                const int cn = (grp + (C) + 2) & 7;                             \
                if (s > 0 && tid == 0) {                                        \
                    while (ld_acq(&g_flag[cn * 32]) < tgt) {}                   \
                }                                                               \
                asm volatile("cp.async.wait_group %0;\n" :: "n"(WG));           \
                __syncthreads();                                                \
                issue_chunk(sA, hin, cn, tid);                                  \
                cp_commit();                                                    \
            } else {                                                            \
                asm volatile("cp.async.wait_group %0;\n" :: "n"(WG));           \
                __syncthreads();                                                \
            }                                                                   \
            _Pragma("unroll")                                                   \
            for (int ks = 0; ks < 4; ks++) {                                    \
                const int kk = cc * 128 + kh * 64 + ks * 16;                    \
                uint32_t a[4];                                                  \
                ldsm4(a, sA + (mw * 16 + (lane & 15)) * 1032                    \
                           + kk + ((lane >> 4) << 3));                          \
                _Pragma("unroll")                                               \
                for (int n2 = 0; n2 < 2; n2++) {                                \
                    uint32_t b[4];                                              \
                    int nr = n2 * 16 + (lane & 7) + ((lane >> 4) << 3);         \
                    ldsm4(b, wsm + nr * 1032 + kk + ((lane >> 3) & 1) * 8);     \
                    mma16816(acc[n2 * 2 + 0], a, b[0], b[1]);                   \
                    mma16816(acc[n2 * 2 + 1], a, b[2], b[3]);                   \
                }                                                               \
            }                                                                   \
        } while (0)

        DO_CHUNK(0, 1);
        DO_CHUNK(1, 1);
        DO_CHUNK(2, 1);
        DO_CHUNK(3, 1);
        DO_CHUNK(4, 1);
        DO_CHUNK(5, 1);
        DO_CHUNK(6, 1);
        DO_CHUNK(7, 0);
#undef DO_CHUNK

        // stage accumulators (two K-half buffers) for cross-gate gather
        {
            float* gw = (kh ? gsm1 : gsm0) + mw * (16 * 33);
            int r = lane >> 2;
#pragma unroll
            for (int nt = 0; nt < 4; nt++) {
                int ci = nt * 8 + ((lane & 3) << 1);
                gw[r * 33 + ci]           = acc[nt][0];
                gw[r * 33 + ci + 1]       = acc[nt][1];
                gw[(r + 8) * 33 + ci]     = acc[nt][2];
                gw[(r + 8) * 33 + ci + 1] = acc[nt][3];
            }
        }
        __syncthreads();

        // LSTM elementwise update: 256 threads x 2 cells
        {
            int b   = tid >> 2;                     // batch row 0..63
            int jl0 = (tid & 3) * 2;                // local unit 0,2,4,6
            const float* w0 = gsm0 + (b >> 4) * (16 * 33) + (b & 15) * 33;
            const float* w1 = gsm1 + (b >> 4) * (16 * 33) + (b & 15) * 33;
            const __half* xr = sxw + b * 32;
            float m = enc ? mask[t * 64 + b] : 1.f;
            float hn2[2];

#pragma unroll
            for (int u = 0; u < 2; u++) {
                int jl  = jl0 + u;
                int col = jl * 4;
                float gi = w0[col + 0] + w1[col + 0] + __half2float(xr[col + 0]);
                float gf = w0[col + 1] + w1[col + 1] + __half2float(xr[col + 1]);
                float gg = w0[col + 2] + w1[col + 2] + __half2float(xr[col + 2]);
                float go = w0[col + 3] + w1[col + 3] + __half2float(xr[col + 3]);

                float ii = sigmoidf_(gi);
                float ff = sigmoidf_(gf);
                float g2 = tanhf_(gg);
                float oo = sigmoidf_(go);

                int   j  = c0 / 4 + jl;             // global hidden unit
                int   ci = b * 8 + jl;              // c-state index (SMEM)
                float cp = csm[ci];
                float cn = ff * cp + ii * g2;
                float hn = oo * tanhf_(cn);

                if (enc) {
                    float hp = __half2float(sA[b * 1032 + j]);  // prev h from SMEM
                    hn = hn * m + hp * (1.f - m);
                    cn = cn * m + cp * (1.f - m);
                }
                csm[ci] = cn;
                hn2[u]  = hn;
            }
            int j0 = c0 / 4 + jl0;
            *reinterpret_cast<__half2*>(hout + b * NH_ + j0) =
                __floats2half2_rn(hn2[0], hn2[1]);
            if (!enc) {
                *reinterpret_cast<float2*>(outp + (size_t)(t * 64 + b) * NH_ + j0) =
                    make_float2(hn2[0], hn2[1]);
            }
        }
        __syncthreads();                      // all stores done before publish
        if (tid == 0) {
            red_rel_add(&g_flag[grp * 32], 1u);
        }
    }
}

// ---------------------------------------------------------------------------
// Launch
// ---------------------------------------------------------------------------
extern "C" void kernel_launch(void* const* d_in, const int* in_sizes, int n_in,
                              void* d_out, int out_size) {
    (void)in_sizes; (void)n_in; (void)out_size;
    const float* input = (const float*)d_in[0];
    const float* mask  = (const float*)d_in[1];
    const float* Wih_e = (const float*)d_in[2];
    const float* Whh_e = (const float*)d_in[3];
    const float* bih_e = (const float*)d_in[4];
    const float* bhh_e = (const float*)d_in[5];
    const float* Wih_d = (const float*)d_in[6];
    const float* Whh_d = (const float*)d_in[7];
    const float* bih_d = (const float*)d_in[8];
    const float* bhh_d = (const float*)d_in[9];
    float* out = (float*)d_out;

    cudaFuncSetAttribute(k_persist, cudaFuncAttributeMaxDynamicSharedMemorySize,
                         SMEM_PERSIST);

    // prep: fp16 conversions, gate-interleaved weight permutation, state reset
    k_convert_x<<<(TB_ * NI_) / 4 / 256, 256>>>(input);
    k_prep<<<2048, 256>>>(Wih_e, Whh_e, bih_e, bhh_e, Wih_d, Whh_d, bih_d, bhh_d);
    k_init<<<(B_ * NH_ + 255) / 256, 256>>>();

    // batched input projections (biases folded in), enc+dec in one launch
    dim3 ggrid(NG_ / 64, TB_ / 64, 2);
    k_xw_gemm<<<ggrid, 128>>>();

    // single persistent kernel: 512 encoder + 512 decoder steps
    k_persist<<<NCTA, 256, SMEM_PERSIST>>>(mask, out);
}

// round 14
// speedup vs baseline: 1.1312x; 1.1312x over previous
#include <cuda_runtime.h>
#include <cuda_fp16.h>
#include <cstdint>

// Problem constants
#define T_  512
#define B_  64
#define NI_ 512
#define NH_ 1024
#define NG_ 4096          // 4*NH
#define TB_ (T_*B_)       // 32768
#define NCTA 128

// ---------------------------------------------------------------------------
// Device scratch (static — no allocations anywhere)
// ---------------------------------------------------------------------------
__device__ __align__(16) __half g_x16[TB_ * NI_];              //  32 MB fp16 input
__device__ __align__(16) __half g_wih[2][NG_ * NI_];           // permuted W_ih [p][k]
__device__ __align__(16) __half g_whh[2][NG_ * NH_];           // permuted W_hh [p][k]
__device__ __align__(16) float  g_bias[2][NG_];                // b_ih+b_hh, permuted
__device__ __align__(16) __half g_xw[2][(size_t)TB_ * NG_];    // 536 MB x@W_ih^T + biases
__device__ __align__(16) __half g_h16[2][B_ * NH_];            // h ping-pong (fp16)
__device__ unsigned g_bar_count;
__device__ unsigned g_bar_gen;

// ---------------------------------------------------------------------------
// PTX helpers
// ---------------------------------------------------------------------------
__device__ __forceinline__ void cp16(void* dst, const void* src) {
    uint32_t d = (uint32_t)__cvta_generic_to_shared(dst);
    asm volatile("cp.async.cg.shared.global [%0], [%1], 16;\n" :: "r"(d), "l"(src));
}
__device__ __forceinline__ void cp_commit() {
    asm volatile("cp.async.commit_group;\n");
}
__device__ __forceinline__ void ldsm4(uint32_t* r, const void* p) {
    uint32_t a = (uint32_t)__cvta_generic_to_shared(p);
    asm volatile("ldmatrix.sync.aligned.m8n8.x4.shared.b16 {%0,%1,%2,%3}, [%4];\n"
                 : "=r"(r[0]), "=r"(r[1]), "=r"(r[2]), "=r"(r[3]) : "r"(a));
}
__device__ __forceinline__ void mma16816(float* c, const uint32_t* a, uint32_t b0, uint32_t b1) {
    asm volatile(
        "mma.sync.aligned.m16n8k16.row.col.f32.f16.f16.f32 "
        "{%0,%1,%2,%3},{%4,%5,%6,%7},{%8,%9},{%0,%1,%2,%3};\n"
        : "+f"(c[0]), "+f"(c[1]), "+f"(c[2]), "+f"(c[3])
        : "r"(a[0]), "r"(a[1]), "r"(a[2]), "r"(a[3]), "r"(b0), "r"(b1));
}
__device__ __forceinline__ float sigmoidf_(float x) {
    return 1.f / (1.f + __expf(-x));
}
__device__ __forceinline__ float tanhf_(float x) {
    x = fminf(fmaxf(x, -15.f), 15.f);
    float e = __expf(2.f * x);
    return (e - 1.f) / (e + 1.f);
}

// ---------------------------------------------------------------------------
// Prep kernels
// ---------------------------------------------------------------------------
__global__ void k_convert_x(const float* __restrict__ x) {
    int i = (blockIdx.x * blockDim.x + threadIdx.x) * 4;
    float4 v = *reinterpret_cast<const float4*>(x + i);
    *reinterpret_cast<__half2*>(g_x16 + i)     = __floats2half2_rn(v.x, v.y);
    *reinterpret_cast<__half2*>(g_x16 + i + 2) = __floats2half2_rn(v.z, v.w);
}

// Permutation: p = 4*j + g  <->  original row r = g*NH + j   (gate order i,f,g,o)
__global__ void k_prep(const float* __restrict__ wih_e, const float* __restrict__ whh_e,
                       const float* __restrict__ bih_e, const float* __restrict__ bhh_e,
                       const float* __restrict__ wih_d, const float* __restrict__ whh_d,
                       const float* __restrict__ bih_d, const float* __restrict__ bhh_d) {
    const long total = 2L * NG_ * NH_;
    for (long i = (long)blockIdx.x * blockDim.x + threadIdx.x; i < total;
         i += (long)gridDim.x * blockDim.x) {
        int  e   = (i >= (long)NG_ * NH_);
        long rem = i - (long)e * NG_ * NH_;
        int  p   = (int)(rem >> 10);
        int  k   = (int)(rem & (NH_ - 1));
        int  r   = ((p & 3) << 10) + (p >> 2);        // g*1024 + j
        const float* whh = e ? whh_d : whh_e;
        g_whh[e][p * NH_ + k] = __float2half(whh[r * NH_ + k]);
        if (k < NI_) {
            const float* wih = e ? wih_d : wih_e;
            g_wih[e][p * NI_ + k] = __float2half(wih[r * NI_ + k]);
        }
        if (k == 0) {
            g_bias[e][p] = e ? (bih_d[r] + bhh_d[r]) : (bih_e[r] + bhh_e[r]);
        }
    }
}

__global__ void k_init() {
    int i = blockIdx.x * blockDim.x + threadIdx.x;
    if (i < B_ * NH_) {
        g_h16[0][i] = __float2half(0.f);
    }
    if (i == 0) {
        g_bar_count = 0u;
        g_bar_gen   = 0u;
    }
}

// ---------------------------------------------------------------------------
// Input projection GEMM: g_xw[e][tb][p] = x16[tb]·Wih[p] + bias[p]   (fp16 out)
// Tiles: M64 x N64, K=512 (BK=64, 8 iters). blockIdx.z = enc/dec.
// ---------------------------------------------------------------------------
__global__ void __launch_bounds__(128) k_xw_gemm() {
    const int e = blockIdx.z;
    const __half* __restrict__ Bw   = g_wih[e];
    const float*  __restrict__ bias = g_bias[e];
    __half*       __restrict__ outp = g_xw[e];

    __shared__ __align__(16) __half sA[2][64][72];
    __shared__ __align__(16) __half sB[2][64][72];

    int tid = threadIdx.x, warp = tid >> 5, lane = tid & 31;
    int mb = blockIdx.y * 64, nb = blockIdx.x * 64;

    float acc[8][4];
#pragma unroll
    for (int i = 0; i < 8; i++)
#pragma unroll
        for (int j = 0; j < 4; j++) acc[i][j] = 0.f;

#pragma unroll
    for (int c = tid; c < 512; c += 128) {
        int r = c >> 3, o = (c & 7) * 8;
        cp16(&sA[0][r][o], g_x16 + (mb + r) * NI_ + o);
    }
#pragma unroll
    for (int c = tid; c < 512; c += 128) {
        int r = c >> 3, o = (c & 7) * 8;
        cp16(&sB[0][r][o], Bw + (nb + r) * NI_ + o);
    }
    cp_commit();

    for (int kt = 0; kt < 8; kt++) {
        if (kt + 1 < 8) {
            int st = (kt + 1) & 1, k0 = (kt + 1) * 64;
#pragma unroll
            for (int c = tid; c < 512; c += 128) {
                int r = c >> 3, o = (c & 7) * 8;
                cp16(&sA[st][r][o], g_x16 + (mb + r) * NI_ + k0 + o);
            }
#pragma unroll
            for (int c = tid; c < 512; c += 128) {
                int r = c >> 3, o = (c & 7) * 8;
                cp16(&sB[st][r][o], Bw + (nb + r) * NI_ + k0 + o);
            }
            cp_commit();
            asm volatile("cp.async.wait_group 1;\n");
        } else {
            asm volatile("cp.async.wait_group 0;\n");
        }
        __syncthreads();
        int st = kt & 1;
#pragma unroll
        for (int ks = 0; ks < 4; ks++) {
            uint32_t a[4];
            ldsm4(a, &sA[st][warp * 16 + (lane & 15)][ks * 16 + ((lane >> 4) << 3)]);
#pragma unroll
            for (int n2 = 0; n2 < 4; n2++) {
                uint32_t b[4];
                int nr = n2 * 16 + (lane & 7) + ((lane >> 4) << 3);
                int kc = ks * 16 + ((lane >> 3) & 1) * 8;
                ldsm4(b, &sB[st][nr][kc]);
                mma16816(acc[n2 * 2 + 0], a, b[0], b[1]);
                mma16816(acc[n2 * 2 + 1], a, b[2], b[3]);
            }
        }
        __syncthreads();
    }

    int r0 = mb + warp * 16 + (lane >> 2);
#pragma unroll
    for (int nt = 0; nt < 8; nt++) {
        int cg = nb + nt * 8 + ((lane & 3) << 1);
        float b0 = bias[cg], b1 = bias[cg + 1];
        __half2 v0 = __floats2half2_rn(acc[nt][0] + b0, acc[nt][1] + b1);
        __half2 v1 = __floats2half2_rn(acc[nt][2] + b0, acc[nt][3] + b1);
        *reinterpret_cast<__half2*>(outp + (size_t)r0 * NG_ + cg)       = v0;
        *reinterpret_cast<__half2*>(outp + (size_t)(r0 + 8) * NG_ + cg) = v1;
    }
}

// ---------------------------------------------------------------------------
// Persistent step kernel. 128 CTAs x 256 threads (8 warps: 4-way M-split x
// 2-way K-split), one CTA per SM. CTA bx owns permuted gate cols
// [32bx,32bx+32) = hidden units [8bx,8bx+8).
// Per step: the FULL h operand (64x1024 fp16, 132KB) is loaded into SMEM as 4
// cp.async groups of 256 columns each (group0 also carries the xw tile), all
// issued immediately after the step barrier (max MLP, no per-chunk gating).
// Pair p computes after wait_group(3-p) + one syncthreads -> 4 syncs/step.
// Current-phase W_hh slice (32x1024, 66KB) stays SMEM-resident; c-state in
// SMEM. Steps separated by ONE global atomic generation barrier (R10-style).
// SMEM: wsm [32][1032] 66048 | sA [64][1032] 132096 | sxw [64][32] 4096 |
//       gsm0+gsm1 2x[4][16][33] f32 16896 | csm [64][8] f32 2048 = 221184 B
// ---------------------------------------------------------------------------
#define SMEM_PERSIST 221184

__global__ void __launch_bounds__(256, 1) k_persist(const float* __restrict__ mask,
                                                    float* __restrict__ outp) {
    extern __shared__ __align__(16) unsigned char smem_raw[];
    __half* wsm  = reinterpret_cast<__half*>(smem_raw);       // [32][1032]
    __half* sA   = wsm + 32 * 1032;                           // [64][1032]
    __half* sxw  = sA + 64 * 1032;                            // [64][32]
    float*  gsm0 = reinterpret_cast<float*>(sxw + 64 * 32);   // [4][16][33]
    float*  gsm1 = gsm0 + 4 * 16 * 33;                        // [4][16][33]
    float*  csm  = gsm1 + 4 * 16 * 33;                        // [64][8]

    const int tid  = threadIdx.x, warp = tid >> 5, lane = tid & 31;
    const int mw   = warp & 3;          // M-row group (rows 16*mw..)
    const int kh   = warp >> 2;         // K-half within each 256-col pair
    const int cta  = blockIdx.x;
    const int c0   = cta * 32;

    // zero c-state (CTA-local, SMEM-resident)
    for (int i = tid; i < 64 * 8; i += 256) csm[i] = 0.f;

    for (int s = 0; s < 1024; s++) {
        const bool enc = (s < 512);
        const int  t   = enc ? s : s - 512;
        const int  e   = enc ? 0 : 1;
        const __half* __restrict__ hin  = g_h16[s & 1];
        __half*       __restrict__ hout = g_h16[(s + 1) & 1];

        // phase start: load this CTA's W_hh slice (enc at s=0, dec at s=512)
        if (s == 0 || s == 512) {
            __syncthreads();   // prior-step mma fully done before overwrite
            const __half* src = g_whh[e] + (size_t)c0 * NH_;
            for (int i = tid; i < 32 * 128; i += 256) {
                int r = i >> 7, ch = i & 127;
                cp16(wsm + r * 1032 + ch * 8, src + r * NH_ + ch * 8);
            }
            cp_commit();
            asm volatile("cp.async.wait_group 0;\n");
            __syncthreads();
        }

        // ---- issue ALL loads up front: 4 groups of 256 h-cols (g0 + xw) ----
        {
            const __half* xwsrc = g_xw[e] + (size_t)(t * 64) * NG_ + c0;
            int b = tid >> 2, o = (tid & 3) * 8;
            cp16(sxw + b * 32 + o, xwsrc + (size_t)b * NG_ + o);
#pragma unroll
            for (int g = 0; g < 4; g++) {
#pragma unroll
                for (int i = tid; i < 2048; i += 256) {
                    int r = i >> 5, off = (i & 31) * 8;
                    cp16(sA + r * 1032 + g * 256 + off,
                         hin + r * NH_ + g * 256 + off);
                }
                cp_commit();
            }
        }

        float acc[4][4];
#pragma unroll
        for (int i = 0; i < 4; i++)
#pragma unroll
            for (int j = 0; j < 4; j++) acc[i][j] = 0.f;

        // pair p (256 cols) after its group lands; warp kh takes 128 of them
#define DO_PAIR(P, WG)                                                          \
        do {                                                                    \
            asm volatile("cp.async.wait_group %0;\n" :: "n"(WG));               \
            __syncthreads();                                                    \
            _Pragma("unroll")                                                   \
            for (int ks = 0; ks < 8; ks++) {                                    \
                const int kk = (P) * 256 + kh * 128 + ks * 16;                  \
                uint32_t a[4];                                                  \
                ldsm4(a, sA + (mw * 16 + (lane & 15)) * 1032                    \
                           + kk + ((lane >> 4) << 3));                          \
                _Pragma("unroll")                                               \
                for (int n2 = 0; n2 < 2; n2++) {                                \
                    uint32_t b[4];                                              \
                    int nr = n2 * 16 + (lane & 7) + ((lane >> 4) << 3);         \
                    ldsm4(b, wsm + nr * 1032 + kk + ((lane >> 3) & 1) * 8);     \
                    mma16816(acc[n2 * 2 + 0], a, b[0], b[1]);                   \
                    mma16816(acc[n2 * 2 + 1], a, b[2], b[3]);                   \
                }                                                               \
            }                                                                   \
        } while (0)

        DO_PAIR(0, 3);
        DO_PAIR(1, 2);
        DO_PAIR(2, 1);
        DO_PAIR(3, 0);
#undef DO_PAIR

        // stage accumulators (two K-half buffers) for cross-gate gather
        {
            float* gw = (kh ? gsm1 : gsm0) + mw * (16 * 33);
            int r = lane >> 2;
#pragma unroll
            for (int nt = 0; nt < 4; nt++) {
                int ci = nt * 8 + ((lane & 3) << 1);
                gw[r * 33 + ci]           = acc[nt][0];
                gw[r * 33 + ci + 1]       = acc[nt][1];
                gw[(r + 8) * 33 + ci]     = acc[nt][2];
                gw[(r + 8) * 33 + ci + 1] = acc[nt][3];
            }
        }
        __syncthreads();

        // LSTM elementwise update: 256 threads x 2 cells
        {
            int b   = tid >> 2;                     // batch row 0..63
            int jl0 = (tid & 3) * 2;                // local unit 0,2,4,6
            const float* w0 = gsm0 + (b >> 4) * (16 * 33) + (b & 15) * 33;
            const float* w1 = gsm1 + (b >> 4) * (16 * 33) + (b & 15) * 33;
            const __half* xr = sxw + b * 32;
            float m = enc ? mask[t * 64 + b] : 1.f;
            float hn2[2];

#pragma unroll
            for (int u = 0; u < 2; u++) {
                int jl  = jl0 + u;
                int col = jl * 4;
                float gi = w0[col + 0] + w1[col + 0] + __half2float(xr[col + 0]);
                float gf = w0[col + 1] + w1[col + 1] + __half2float(xr[col + 1]);
                float gg = w0[col + 2] + w1[col + 2] + __half2float(xr[col + 2]);
                float go = w0[col + 3] + w1[col + 3] + __half2float(xr[col + 3]);

                float ii = sigmoidf_(gi);
                float ff = sigmoidf_(gf);
                float g2 = tanhf_(gg);
                float oo = sigmoidf_(go);

                int   j  = c0 / 4 + jl;             // global hidden unit
                int   ci = b * 8 + jl;              // c-state index (SMEM)
                float cp = csm[ci];
                float cn = ff * cp + ii * g2;
                float hn = oo * tanhf_(cn);

                if (enc) {
                    float hp = __half2float(sA[b * 1032 + j]);  // prev h from SMEM
                    hn = hn * m + hp * (1.f - m);
                    cn = cn * m + cp * (1.f - m);
                }
                csm[ci] = cn;
                hn2[u]  = hn;
            }
            int j0 = c0 / 4 + jl0;
            *reinterpret_cast<__half2*>(hout + b * NH_ + j0) =
                __floats2half2_rn(hn2[0], hn2[1]);
            if (!enc) {
                *reinterpret_cast<float2*>(outp + (size_t)(t * 64 + b) * NH_ + j0) =
                    make_float2(hn2[0], hn2[1]);
            }
        }

        // ---- grid barrier (release h writes, acquire peers') ----
        if (s != 1023) {
            __threadfence();
            __syncthreads();
            if (tid == 0) {
                unsigned a = atomicAdd(&g_bar_count, 1u);
                if (a == NCTA - 1) {
                    g_bar_count = 0u;
                    __threadfence();
                    atomicAdd(&g_bar_gen, 1u);
                } else {
                    unsigned target = (unsigned)(s + 1);
                    while (*((volatile unsigned*)&g_bar_gen) < target) {
                        __nanosleep(32);
                    }
                }
                __threadfence();
            }
            __syncthreads();
        }
    }
}

// ---------------------------------------------------------------------------
// Launch
// ---------------------------------------------------------------------------
extern "C" void kernel_launch(void* const* d_in, const int* in_sizes, int n_in,
                              void* d_out, int out_size) {
    (void)in_sizes; (void)n_in; (void)out_size;
    const float* input = (const float*)d_in[0];
    const float* mask  = (const float*)d_in[1];
    const float* Wih_e = (const float*)d_in[2];
    const float* Whh_e = (const float*)d_in[3];
    const float* bih_e = (const float*)d_in[4];
    const float* bhh_e = (const float*)d_in[5];
    const float* Wih_d = (const float*)d_in[6];
    const float* Whh_d = (const float*)d_in[7];
    const float* bih_d = (const float*)d_in[8];
    const float* bhh_d = (const float*)d_in[9];
    float* out = (float*)d_out;

    cudaFuncSetAttribute(k_persist, cudaFuncAttributeMaxDynamicSharedMemorySize,
                         SMEM_PERSIST);

    // prep: fp16 conversions, gate-interleaved weight permutation, state reset
    k_convert_x<<<(TB_ * NI_) / 4 / 256, 256>>>(input);
    k_prep<<<2048, 256>>>(Wih_e, Whh_e, bih_e, bhh_e, Wih_d, Whh_d, bih_d, bhh_d);
    k_init<<<(B_ * NH_ + 255) / 256, 256>>>();

    // batched input projections (biases folded in), enc+dec in one launch
    dim3 ggrid(NG_ / 64, TB_ / 64, 2);
    k_xw_gemm<<<ggrid, 128>>>();

    // single persistent kernel: 512 encoder + 512 decoder steps
    k_persist<<<NCTA, 256, SMEM_PERSIST>>>(mask, out);
}

// round 15
// speedup vs baseline: 1.3312x; 1.1767x over previous
#include <cuda_runtime.h>
#include <cuda_fp16.h>
#include <cstdint>

// Problem constants
#define T_  512
#define B_  64
#define NI_ 512
#define NH_ 1024
#define NG_ 4096          // 4*NH
#define TB_ (T_*B_)       // 32768
#define NCTA 128

// ---------------------------------------------------------------------------
// Device scratch (static — no allocations anywhere)
// ---------------------------------------------------------------------------
__device__ __align__(16) __half g_x16[TB_ * NI_];              //  32 MB fp16 input
__device__ __align__(16) __half g_wih[2][NG_ * NI_];           // permuted W_ih [p][k]
__device__ __align__(16) __half g_whh[2][NG_ * NH_];           // permuted W_hh [p][k]
__device__ __align__(16) float  g_bias[2][NG_];                // b_ih+b_hh, permuted
__device__ __align__(16) __half g_xw[2][(size_t)TB_ * NG_];    // 536 MB x@W_ih^T + biases
__device__ __align__(16) __half g_h16[2][B_ * NH_];            // h ping-pong (fp16)
__device__ __align__(128) unsigned g_flag[8 * 32];             // 8 group flags, 128B apart

// ---------------------------------------------------------------------------
// PTX helpers
// ---------------------------------------------------------------------------
__device__ __forceinline__ void cp16(void* dst, const void* src) {
    uint32_t d = (uint32_t)__cvta_generic_to_shared(dst);
    asm volatile("cp.async.cg.shared.global [%0], [%1], 16;\n" :: "r"(d), "l"(src));
}
__device__ __forceinline__ void cp_commit() {
    asm volatile("cp.async.commit_group;\n");
}
__device__ __forceinline__ void ldsm4(uint32_t* r, const void* p) {
    uint32_t a = (uint32_t)__cvta_generic_to_shared(p);
    asm volatile("ldmatrix.sync.aligned.m8n8.x4.shared.b16 {%0,%1,%2,%3}, [%4];\n"
                 : "=r"(r[0]), "=r"(r[1]), "=r"(r[2]), "=r"(r[3]) : "r"(a));
}
__device__ __forceinline__ void mma16816(float* c, const uint32_t* a, uint32_t b0, uint32_t b1) {
    asm volatile(
        "mma.sync.aligned.m16n8k16.row.col.f32.f16.f16.f32 "
        "{%0,%1,%2,%3},{%4,%5,%6,%7},{%8,%9},{%0,%1,%2,%3};\n"
        : "+f"(c[0]), "+f"(c[1]), "+f"(c[2]), "+f"(c[3])
        : "r"(a[0]), "r"(a[1]), "r"(a[2]), "r"(a[3]), "r"(b0), "r"(b1));
}
__device__ __forceinline__ unsigned ld_acq(const unsigned* p) {
    unsigned v;
    asm volatile("ld.acquire.gpu.u32 %0, [%1];" : "=r"(v) : "l"(p) : "memory");
    return v;
}
__device__ __forceinline__ void red_rel_add(unsigned* p, unsigned v) {
    asm volatile("red.release.gpu.add.u32 [%0], %1;" :: "l"(p), "r"(v) : "memory");
}
__device__ __forceinline__ float sigmoidf_(float x) {
    return 1.f / (1.f + __expf(-x));
}
__device__ __forceinline__ float tanhf_(float x) {
    x = fminf(fmaxf(x, -15.f), 15.f);
    float e = __expf(2.f * x);
    return (e - 1.f) / (e + 1.f);
}

// ---------------------------------------------------------------------------
// Prep kernels
// ---------------------------------------------------------------------------
__global__ void k_convert_x(const float* __restrict__ x) {
    int i = (blockIdx.x * blockDim.x + threadIdx.x) * 4;
    float4 v = *reinterpret_cast<const float4*>(x + i);
    *reinterpret_cast<__half2*>(g_x16 + i)     = __floats2half2_rn(v.x, v.y);
    *reinterpret_cast<__half2*>(g_x16 + i + 2) = __floats2half2_rn(v.z, v.w);
}

// Permutation: p = 4*j + g  <->  original row r = g*NH + j   (gate order i,f,g,o)
__global__ void k_prep(const float* __restrict__ wih_e, const float* __restrict__ whh_e,
                       const float* __restrict__ bih_e, const float* __restrict__ bhh_e,
                       const float* __restrict__ wih_d, const float* __restrict__ whh_d,
                       const float* __restrict__ bih_d, const float* __restrict__ bhh_d) {
    const long total = 2L * NG_ * NH_;
    for (long i = (long)blockIdx.x * blockDim.x + threadIdx.x; i < total;
         i += (long)gridDim.x * blockDim.x) {
        int  e   = (i >= (long)NG_ * NH_);
        long rem = i - (long)e * NG_ * NH_;
        int  p   = (int)(rem >> 10);
        int  k   = (int)(rem & (NH_ - 1));
        int  r   = ((p & 3) << 10) + (p >> 2);        // g*1024 + j
        const float* whh = e ? whh_d : whh_e;
        g_whh[e][p * NH_ + k] = __float2half(whh[r * NH_ + k]);
        if (k < NI_) {
            const float* wih = e ? wih_d : wih_e;
            g_wih[e][p * NI_ + k] = __float2half(wih[r * NI_ + k]);
        }
        if (k == 0) {
            g_bias[e][p] = e ? (bih_d[r] + bhh_d[r]) : (bih_e[r] + bhh_e[r]);
        }
    }
}

__global__ void k_init() {
    int i = blockIdx.x * blockDim.x + threadIdx.x;
    if (i < B_ * NH_) {
        g_h16[0][i] = __float2half(0.f);
    }
    if (i < 8 * 32) {
        g_flag[i] = 0u;
    }
}

// ---------------------------------------------------------------------------
// Input projection GEMM: g_xw[e][tb][p] = x16[tb]·Wih[p] + bias[p]   (fp16 out)
// Tiles: M128 x N64, K=512 (BK=64, 8 iters), 256 threads (4 M-warps x 2
// N-warps, each warp 32 rows x 32 cols). blockIdx.z = enc/dec.
// Dynamic smem: sA 2x[128][72] + sB 2x[64][72] halves = 55296 B.
// ---------------------------------------------------------------------------
#define SMEM_XW 55296

__global__ void __launch_bounds__(256) k_xw_gemm() {
    const int e = blockIdx.z;
    const __half* __restrict__ Bw   = g_wih[e];
    const float*  __restrict__ bias = g_bias[e];
    __half*       __restrict__ outp = g_xw[e];

    extern __shared__ __align__(16) unsigned char smem_raw[];
    __half* sA = reinterpret_cast<__half*>(smem_raw);   // [2][128][72]
    __half* sB = sA + 2 * 128 * 72;                     // [2][64][72]

    const int tid = threadIdx.x, warp = tid >> 5, lane = tid & 31;
    const int mw2 = warp & 3;          // M group: rows 32*mw2..+31
    const int nh  = warp >> 2;         // N half: cols 32*nh..+31
    const int mb = blockIdx.y * 128, nb = blockIdx.x * 64;

    float acc[2][4][4];
#pragma unroll
    for (int a = 0; a < 2; a++)
#pragma unroll
        for (int i = 0; i < 4; i++)
#pragma unroll
            for (int j = 0; j < 4; j++) acc[a][i][j] = 0.f;

    // prologue: stage 0
#pragma unroll
    for (int c = tid; c < 1024; c += 256) {
        int r = c >> 3, o = (c & 7) * 8;
        cp16(sA + r * 72 + o, g_x16 + (mb + r) * NI_ + o);
    }
#pragma unroll
    for (int c = tid; c < 512; c += 256) {
        int r = c >> 3, o = (c & 7) * 8;
        cp16(sB + r * 72 + o, Bw + (nb + r) * NI_ + o);
    }
    cp_commit();

    for (int kt = 0; kt < 8; kt++) {
        if (kt + 1 < 8) {
            int st = (kt + 1) & 1, k0 = (kt + 1) * 64;
#pragma unroll
            for (int c = tid; c < 1024; c += 256) {
                int r = c >> 3, o = (c & 7) * 8;
                cp16(sA + st * (128 * 72) + r * 72 + o,
                     g_x16 + (mb + r) * NI_ + k0 + o);
            }
#pragma unroll
            for (int c = tid; c < 512; c += 256) {
                int r = c >> 3, o = (c & 7) * 8;
                cp16(sB + st * (64 * 72) + r * 72 + o, Bw + (nb + r) * NI_ + k0 + o);
            }
            cp_commit();
            asm volatile("cp.async.wait_group 1;\n");
        } else {
            asm volatile("cp.async.wait_group 0;\n");
        }
        __syncthreads();
        const __half* A = sA + (kt & 1) * (128 * 72);
        const __half* Bs = sB + (kt & 1) * (64 * 72);
#pragma unroll
        for (int ks = 0; ks < 4; ks++) {
            uint32_t a[2][4];
#pragma unroll
            for (int at = 0; at < 2; at++) {
                ldsm4(a[at], A + (mw2 * 32 + at * 16 + (lane & 15)) * 72
                               + ks * 16 + ((lane >> 4) << 3));
            }
#pragma unroll
            for (int bt = 0; bt < 2; bt++) {
                uint32_t b[4];
                int nr = nh * 32 + bt * 16 + (lane & 7) + ((lane >> 4) << 3);
                int kc = ks * 16 + ((lane >> 3) & 1) * 8;
                ldsm4(b, Bs + nr * 72 + kc);
#pragma unroll
                for (int at = 0; at < 2; at++) {
                    mma16816(acc[at][bt * 2 + 0], a[at], b[0], b[1]);
                    mma16816(acc[at][bt * 2 + 1], a[at], b[2], b[3]);
                }
            }
        }
        __syncthreads();
    }

#pragma unroll
    for (int at = 0; at < 2; at++) {
        int r0 = mb + mw2 * 32 + at * 16 + (lane >> 2);
#pragma unroll
        for (int nt = 0; nt < 4; nt++) {
            int cg = nb + nh * 32 + nt * 8 + ((lane & 3) << 1);
            float b0 = bias[cg], b1 = bias[cg + 1];
            __half2 v0 = __floats2half2_rn(acc[at][nt][0] + b0, acc[at][nt][1] + b1);
            __half2 v1 = __floats2half2_rn(acc[at][nt][2] + b0, acc[at][nt][3] + b1);
            *reinterpret_cast<__half2*>(outp + (size_t)r0 * NG_ + cg)       = v0;
            *reinterpret_cast<__half2*>(outp + (size_t)(r0 + 8) * NG_ + cg) = v1;
        }
    }
}

// ---------------------------------------------------------------------------
// Persistent step kernel. 128 CTAs x 256 threads (8 warps: 4-way M-split x
// 2-way K-split), one CTA per SM. CTA bx owns permuted gate cols
// [32bx,32bx+32) = hidden units [8bx,8bx+8).
// Identical dataflow to R14 (issue all 4 h-groups after one wait point, pair p
// computes after wait_group(3-p)); ONLY the inter-step barrier changed:
// distributed arrival on 8 per-group flags (16 CTAs red.release.add each, on
// separate 128B lines) + lane-parallel acquire-spin on all 8 flags. This is a
// full barrier (arrival is end-of-step, after all reads), with 8-way parallel
// arrival instead of 128 serialized same-address atomics.
// SMEM: wsm [32][1032] 66048 | sA [64][1032] 132096 | sxw [64][32] 4096 |
//       gsm0+gsm1 2x[4][16][33] f32 16896 | csm [64][8] f32 2048 = 221184 B
// ---------------------------------------------------------------------------
#define SMEM_PERSIST 221184

__global__ void __launch_bounds__(256, 1) k_persist(const float* __restrict__ mask,
                                                    float* __restrict__ outp) {
    extern __shared__ __align__(16) unsigned char smem_raw[];
    __half* wsm  = reinterpret_cast<__half*>(smem_raw);       // [32][1032]
    __half* sA   = wsm + 32 * 1032;                           // [64][1032]
    __half* sxw  = sA + 64 * 1032;                            // [64][32]
    float*  gsm0 = reinterpret_cast<float*>(sxw + 64 * 32);   // [4][16][33]
    float*  gsm1 = gsm0 + 4 * 16 * 33;                        // [4][16][33]
    float*  csm  = gsm1 + 4 * 16 * 33;                        // [64][8]

    const int tid  = threadIdx.x, warp = tid >> 5, lane = tid & 31;
    const int mw   = warp & 3;          // M-row group (rows 16*mw..)
    const int kh   = warp >> 2;         // K-half within each 256-col pair
    const int cta  = blockIdx.x;
    const int c0   = cta * 32;
    const int grp  = cta >> 4;          // arrival flag group

    // zero c-state (CTA-local, SMEM-resident)
    for (int i = tid; i < 64 * 8; i += 256) csm[i] = 0.f;

    for (int s = 0; s < 1024; s++) {
        const bool enc = (s < 512);
        const int  t   = enc ? s : s - 512;
        const int  e   = enc ? 0 : 1;
        const __half* __restrict__ hin  = g_h16[s & 1];
        __half*       __restrict__ hout = g_h16[(s + 1) & 1];

        // ---- wait: all 8 group flags reached 16*s (full barrier) ----
        if (s > 0) {
            if (tid < 8) {
                const unsigned tgt = 16u * (unsigned)s;
                while (ld_acq(&g_flag[tid * 32]) < tgt) {}
            }
            __syncthreads();
        }

        // phase start: load this CTA's W_hh slice (enc at s=0, dec at s=512)
        if (s == 0 || s == 512) {
            __syncthreads();   // prior-step mma fully done before overwrite
            const __half* src = g_whh[e] + (size_t)c0 * NH_;
            for (int i = tid; i < 32 * 128; i += 256) {
                int r = i >> 7, ch = i & 127;
                cp16(wsm + r * 1032 + ch * 8, src + r * NH_ + ch * 8);
            }
            cp_commit();
            asm volatile("cp.async.wait_group 0;\n");
            __syncthreads();
        }

        // ---- issue ALL loads up front: 4 groups of 256 h-cols (g0 + xw) ----
        {
            const __half* xwsrc = g_xw[e] + (size_t)(t * 64) * NG_ + c0;
            int b = tid >> 2, o = (tid & 3) * 8;
            cp16(sxw + b * 32 + o, xwsrc + (size_t)b * NG_ + o);
#pragma unroll
            for (int g = 0; g < 4; g++) {
#pragma unroll
                for (int i = tid; i < 2048; i += 256) {
                    int r = i >> 5, off = (i & 31) * 8;
                    cp16(sA + r * 1032 + g * 256 + off,
                         hin + r * NH_ + g * 256 + off);
                }
                cp_commit();
            }
        }

        float acc[4][4];
#pragma unroll
        for (int i = 0; i < 4; i++)
#pragma unroll
            for (int j = 0; j < 4; j++) acc[i][j] = 0.f;

        // pair p (256 cols) after its group lands; warp kh takes 128 of them
#define DO_PAIR(P, WG)                                                          \
        do {                                                                    \
            asm volatile("cp.async.wait_group %0;\n" :: "n"(WG));               \
            __syncthreads();                                                    \
            _Pragma("unroll")                                                   \
            for (int ks = 0; ks < 8; ks++) {                                    \
                const int kk = (P) * 256 + kh * 128 + ks * 16;                  \
                uint32_t a[4];                                                  \
                ldsm4(a, sA + (mw * 16 + (lane & 15)) * 1032                    \
                           + kk + ((lane >> 4) << 3));                          \
                _Pragma("unroll")                                               \
                for (int n2 = 0; n2 < 2; n2++) {                                \
                    uint32_t b[4];                                              \
                    int nr = n2 * 16 + (lane & 7) + ((lane >> 4) << 3);         \
                    ldsm4(b, wsm + nr * 1032 + kk + ((lane >> 3) & 1) * 8);     \
                    mma16816(acc[n2 * 2 + 0], a, b[0], b[1]);                   \
                    mma16816(acc[n2 * 2 + 1], a, b[2], b[3]);                   \
                }                                                               \
            }                                                                   \
        } while (0)

        DO_PAIR(0, 3);
        DO_PAIR(1, 2);
        DO_PAIR(2, 1);
        DO_PAIR(3, 0);
#undef DO_PAIR

        // stage accumulators (two K-half buffers) for cross-gate gather
        {
            float* gw = (kh ? gsm1 : gsm0) + mw * (16 * 33);
            int r = lane >> 2;
#pragma unroll
            for (int nt = 0; nt < 4; nt++) {
                int ci = nt * 8 + ((lane & 3) << 1);
                gw[r * 33 + ci]           = acc[nt][0];
                gw[r * 33 + ci + 1]       = acc[nt][1];
                gw[(r + 8) * 33 + ci]     = acc[nt][2];
                gw[(r + 8) * 33 + ci + 1] = acc[nt][3];
            }
        }
        __syncthreads();

        // LSTM elementwise update: 256 threads x 2 cells
        {
            int b   = tid >> 2;                     // batch row 0..63
            int jl0 = (tid & 3) * 2;                // local unit 0,2,4,6
            const float* w0 = gsm0 + (b >> 4) * (16 * 33) + (b & 15) * 33;
            const float* w1 = gsm1 + (b >> 4) * (16 * 33) + (b & 15) * 33;
            const __half* xr = sxw + b * 32;
            float m = enc ? mask[t * 64 + b] : 1.f;
            float hn2[2];

#pragma unroll
            for (int u = 0; u < 2; u++) {
                int jl  = jl0 + u;
                int col = jl * 4;
                float gi = w0[col + 0] + w1[col + 0] + __half2float(xr[col + 0]);
                float gf = w0[col + 1] + w1[col + 1] + __half2float(xr[col + 1]);
                float gg = w0[col + 2] + w1[col + 2] + __half2float(xr[col + 2]);
                float go = w0[col + 3] + w1[col + 3] + __half2float(xr[col + 3]);

                float ii = sigmoidf_(gi);
                float ff = sigmoidf_(gf);
                float g2 = tanhf_(gg);
                float oo = sigmoidf_(go);

                int   j  = c0 / 4 + jl;             // global hidden unit
                int   ci = b * 8 + jl;              // c-state index (SMEM)
                float cp = csm[ci];
                float cn = ff * cp + ii * g2;
                float hn = oo * tanhf_(cn);

                if (enc) {
                    float hp = __half2float(sA[b * 1032 + j]);  // prev h from SMEM
                    hn = hn * m + hp * (1.f - m);
                    cn = cn * m + cp * (1.f - m);
                }
                csm[ci] = cn;
                hn2[u]  = hn;
            }
            int j0 = c0 / 4 + jl0;
            *reinterpret_cast<__half2*>(hout + b * NH_ + j0) =
                __floats2half2_rn(hn2[0], hn2[1]);
            if (!enc) {
                *reinterpret_cast<float2*>(outp + (size_t)(t * 64 + b) * NH_ + j0) =
                    make_float2(hn2[0], hn2[1]);
            }
        }

        // ---- arrival: distributed release (all CTA work, incl. reads, done) ----
        __syncthreads();
        if (tid == 0 && s != 1023) {
            red_rel_add(&g_flag[grp * 32], 1u);
        }
    }
}

// ---------------------------------------------------------------------------
// Launch
// ---------------------------------------------------------------------------
extern "C" void kernel_launch(void* const* d_in, const int* in_sizes, int n_in,
                              void* d_out, int out_size) {
    (void)in_sizes; (void)n_in; (void)out_size;
    const float* input = (const float*)d_in[0];
    const float* mask  = (const float*)d_in[1];
    const float* Wih_e = (const float*)d_in[2];
    const float* Whh_e = (const float*)d_in[3];
    const float* bih_e = (const float*)d_in[4];
    const float* bhh_e = (const float*)d_in[5];
    const float* Wih_d = (const float*)d_in[6];
    const float* Whh_d = (const float*)d_in[7];
    const float* bih_d = (const float*)d_in[8];
    const float* bhh_d = (const float*)d_in[9];
    float* out = (float*)d_out;

    cudaFuncSetAttribute(k_persist, cudaFuncAttributeMaxDynamicSharedMemorySize,
                         SMEM_PERSIST);
    cudaFuncSetAttribute(k_xw_gemm, cudaFuncAttributeMaxDynamicSharedMemorySize,
                         SMEM_XW);

    // prep: fp16 conversions, gate-interleaved weight permutation, state reset
    k_convert_x<<<(TB_ * NI_) / 4 / 256, 256>>>(input);
    k_prep<<<2048, 256>>>(Wih_e, Whh_e, bih_e, bhh_e, Wih_d, Whh_d, bih_d, bhh_d);
    k_init<<<(B_ * NH_ + 255) / 256, 256>>>();

    // batched input projections (biases folded in), enc+dec in one launch
    dim3 ggrid(NG_ / 64, TB_ / 128, 2);
    k_xw_gemm<<<ggrid, 256, SMEM_XW>>>();

    // single persistent kernel: 512 encoder + 512 decoder steps
    k_persist<<<NCTA, 256, SMEM_PERSIST>>>(mask, out);
}

// round 16
// speedup vs baseline: 1.3372x; 1.0045x over previous
#include <cuda_runtime.h>
#include <cuda_fp16.h>
#include <cstdint>

// Problem constants
#define T_  512
#define B_  64
#define NI_ 512
#define NH_ 1024
#define NG_ 4096          // 4*NH
#define TB_ (T_*B_)       // 32768
#define NCTA 128

// ---------------------------------------------------------------------------
// Device scratch (static — no allocations anywhere)
// ---------------------------------------------------------------------------
__device__ __align__(16) __half g_x16[TB_ * NI_];              //  32 MB fp16 input
__device__ __align__(16) __half g_wih[2][NG_ * NI_];           // permuted W_ih [p][k]
__device__ __align__(16) __half g_whh[2][NG_ * NH_];           // permuted W_hh [p][k]
__device__ __align__(16) float  g_bias[2][NG_];                // b_ih+b_hh, permuted
__device__ __align__(16) __half g_xw[2][(size_t)TB_ * NG_];    // 536 MB x@W_ih^T + biases
__device__ __align__(16) __half g_h16[2][B_ * NH_];            // h ping-pong (fp16)
__device__ __align__(128) unsigned g_flag[8 * 32];             // 8 group flags, 128B apart

// ---------------------------------------------------------------------------
// PTX helpers
// ---------------------------------------------------------------------------
__device__ __forceinline__ void cp16(void* dst, const void* src) {
    uint32_t d = (uint32_t)__cvta_generic_to_shared(dst);
    asm volatile("cp.async.cg.shared.global [%0], [%1], 16;\n" :: "r"(d), "l"(src));
}
__device__ __forceinline__ void cp_commit() {
    asm volatile("cp.async.commit_group;\n");
}
__device__ __forceinline__ void ldsm4(uint32_t* r, const void* p) {
    uint32_t a = (uint32_t)__cvta_generic_to_shared(p);
    asm volatile("ldmatrix.sync.aligned.m8n8.x4.shared.b16 {%0,%1,%2,%3}, [%4];\n"
                 : "=r"(r[0]), "=r"(r[1]), "=r"(r[2]), "=r"(r[3]) : "r"(a));
}
__device__ __forceinline__ void mma16816(float* c, const uint32_t* a, uint32_t b0, uint32_t b1) {
    asm volatile(
        "mma.sync.aligned.m16n8k16.row.col.f32.f16.f16.f32 "
        "{%0,%1,%2,%3},{%4,%5,%6,%7},{%8,%9},{%0,%1,%2,%3};\n"
        : "+f"(c[0]), "+f"(c[1]), "+f"(c[2]), "+f"(c[3])
        : "r"(a[0]), "r"(a[1]), "r"(a[2]), "r"(a[3]), "r"(b0), "r"(b1));
}
__device__ __forceinline__ unsigned ld_acq(const unsigned* p) {
    unsigned v;
    asm volatile("ld.acquire.gpu.u32 %0, [%1];" : "=r"(v) : "l"(p) : "memory");
    return v;
}
__device__ __forceinline__ void red_rel_add(unsigned* p, unsigned v) {
    asm volatile("red.release.gpu.add.u32 [%0], %1;" :: "l"(p), "r"(v) : "memory");
}
__device__ __forceinline__ float sigmoidf_(float x) {
    return 1.f / (1.f + __expf(-x));
}
__device__ __forceinline__ float tanhf_(float x) {
    x = fminf(fmaxf(x, -15.f), 15.f);
    float e = __expf(2.f * x);
    return (e - 1.f) / (e + 1.f);
}

// ---------------------------------------------------------------------------
// Prep kernels
// ---------------------------------------------------------------------------
__global__ void k_convert_x(const float* __restrict__ x) {
    int i = (blockIdx.x * blockDim.x + threadIdx.x) * 4;
    float4 v = *reinterpret_cast<const float4*>(x + i);
    *reinterpret_cast<__half2*>(g_x16 + i)     = __floats2half2_rn(v.x, v.y);
    *reinterpret_cast<__half2*>(g_x16 + i + 2) = __floats2half2_rn(v.z, v.w);
}

// Permutation: p = 4*j + g  <->  original row r = g*NH + j   (gate order i,f,g,o)
__global__ void k_prep(const float* __restrict__ wih_e, const float* __restrict__ whh_e,
                       const float* __restrict__ bih_e, const float* __restrict__ bhh_e,
                       const float* __restrict__ wih_d, const float* __restrict__ whh_d,
                       const float* __restrict__ bih_d, const float* __restrict__ bhh_d) {
    const long total = 2L * NG_ * NH_;
    for (long i = (long)blockIdx.x * blockDim.x + threadIdx.x; i < total;
         i += (long)gridDim.x * blockDim.x) {
        int  e   = (i >= (long)NG_ * NH_);
        long rem = i - (long)e * NG_ * NH_;
        int  p   = (int)(rem >> 10);
        int  k   = (int)(rem & (NH_ - 1));
        int  r   = ((p & 3) << 10) + (p >> 2);        // g*1024 + j
        const float* whh = e ? whh_d : whh_e;
        g_whh[e][p * NH_ + k] = __float2half(whh[r * NH_ + k]);
        if (k < NI_) {
            const float* wih = e ? wih_d : wih_e;
            g_wih[e][p * NI_ + k] = __float2half(wih[r * NI_ + k]);
        }
        if (k == 0) {
            g_bias[e][p] = e ? (bih_d[r] + bhh_d[r]) : (bih_e[r] + bhh_e[r]);
        }
    }
}

__global__ void k_init() {
    int i = blockIdx.x * blockDim.x + threadIdx.x;
    if (i < B_ * NH_) {
        g_h16[0][i] = __float2half(0.f);
    }
    if (i < 8 * 32) {
        g_flag[i] = 0u;
    }
}

// ---------------------------------------------------------------------------
// Input projection GEMM: g_xw[e][tb][p] = x16[tb]·Wih[p] + bias[p]   (fp16 out)
// Tiles: M128 x N64, K=512 (BK=64, 8 iters), 256 threads (4 M-warps x 2
// N-warps). blockIdx.z = enc/dec. Unchanged from R15.
// ---------------------------------------------------------------------------
#define SMEM_XW 55296

__global__ void __launch_bounds__(256) k_xw_gemm() {
    const int e = blockIdx.z;
    const __half* __restrict__ Bw   = g_wih[e];
    const float*  __restrict__ bias = g_bias[e];
    __half*       __restrict__ outp = g_xw[e];

    extern __shared__ __align__(16) unsigned char smem_raw[];
    __half* sA = reinterpret_cast<__half*>(smem_raw);   // [2][128][72]
    __half* sB = sA + 2 * 128 * 72;                     // [2][64][72]

    const int tid = threadIdx.x, warp = tid >> 5, lane = tid & 31;
    const int mw2 = warp & 3;
    const int nh  = warp >> 2;
    const int mb = blockIdx.y * 128, nb = blockIdx.x * 64;

    float acc[2][4][4];
#pragma unroll
    for (int a = 0; a < 2; a++)
#pragma unroll
        for (int i = 0; i < 4; i++)
#pragma unroll
            for (int j = 0; j < 4; j++) acc[a][i][j] = 0.f;

#pragma unroll
    for (int c = tid; c < 1024; c += 256) {
        int r = c >> 3, o = (c & 7) * 8;
        cp16(sA + r * 72 + o, g_x16 + (mb + r) * NI_ + o);
    }
#pragma unroll
    for (int c = tid; c < 512; c += 256) {
        int r = c >> 3, o = (c & 7) * 8;
        cp16(sB + r * 72 + o, Bw + (nb + r) * NI_ + o);
    }
    cp_commit();

    for (int kt = 0; kt < 8; kt++) {
        if (kt + 1 < 8) {
            int st = (kt + 1) & 1, k0 = (kt + 1) * 64;
#pragma unroll
            for (int c = tid; c < 1024; c += 256) {
                int r = c >> 3, o = (c & 7) * 8;
                cp16(sA + st * (128 * 72) + r * 72 + o,
                     g_x16 + (mb + r) * NI_ + k0 + o);
            }
#pragma unroll
            for (int c = tid; c < 512; c += 256) {
                int r = c >> 3, o = (c & 7) * 8;
                cp16(sB + st * (64 * 72) + r * 72 + o, Bw + (nb + r) * NI_ + k0 + o);
            }
            cp_commit();
            asm volatile("cp.async.wait_group 1;\n");
        } else {
            asm volatile("cp.async.wait_group 0;\n");
        }
        __syncthreads();
        const __half* A = sA + (kt & 1) * (128 * 72);
        const __half* Bs = sB + (kt & 1) * (64 * 72);
#pragma unroll
        for (int ks = 0; ks < 4; ks++) {
            uint32_t a[2][4];
#pragma unroll
            for (int at = 0; at < 2; at++) {
                ldsm4(a[at], A + (mw2 * 32 + at * 16 + (lane & 15)) * 72
                               + ks * 16 + ((lane >> 4) << 3));
            }
#pragma unroll
            for (int bt = 0; bt < 2; bt++) {
                uint32_t b[4];
                int nr = nh * 32 + bt * 16 + (lane & 7) + ((lane >> 4) << 3);
                int kc = ks * 16 + ((lane >> 3) & 1) * 8;
                ldsm4(b, Bs + nr * 72 + kc);
#pragma unroll
                for (int at = 0; at < 2; at++) {
                    mma16816(acc[at][bt * 2 + 0], a[at], b[0], b[1]);
                    mma16816(acc[at][bt * 2 + 1], a[at], b[2], b[3]);
                }
            }
        }
        __syncthreads();
    }

#pragma unroll
    for (int at = 0; at < 2; at++) {
        int r0 = mb + mw2 * 32 + at * 16 + (lane >> 2);
#pragma unroll
        for (int nt = 0; nt < 4; nt++) {
            int cg = nb + nh * 32 + nt * 8 + ((lane & 3) << 1);
            float b0 = bias[cg], b1 = bias[cg + 1];
            __half2 v0 = __floats2half2_rn(acc[at][nt][0] + b0, acc[at][nt][1] + b1);
            __half2 v1 = __floats2half2_rn(acc[at][nt][2] + b0, acc[at][nt][3] + b1);
            *reinterpret_cast<__half2*>(outp + (size_t)r0 * NG_ + cg)       = v0;
            *reinterpret_cast<__half2*>(outp + (size_t)(r0 + 8) * NG_ + cg) = v1;
        }
    }
}

// ---------------------------------------------------------------------------
// Persistent step kernel. 128 CTAs x 256 threads, one per SM. CTA bx owns
// permuted gate cols [32bx,32bx+32) = hidden units [8bx,8bx+8).
// Warp split: 2-way M (mw: 32 rows) x 4-way K (kh), K interleaved so warp kh
// owns cols p*256 + i*64 + kh*16 (4 chunks inside every 256-col cp group).
// KEY CHANGE vs R15: the W_hh B-fragments live in REGISTERS for the whole
// phase (128 regs/warp, ldsm'd twice per run from a staging pass that reuses
// sA) — per-step SMEM crossbar traffic drops from ~516KB to ~260KB. The xw
// tile prefetch is issued before the inter-step flag wait (no cross-CTA dep).
// Barrier: R15 distributed 8-flag scheme, unchanged.
// SMEM: sA [64][1032] 132096 | sxw [64][32] 4096 | gsm 4x[64][33] f32 33792 |
//       csm [64][8] f32 2048 = 172032 B
// ---------------------------------------------------------------------------
#define SMEM_PERSIST 172032

__global__ void __launch_bounds__(256, 1) k_persist(const float* __restrict__ mask,
                                                    float* __restrict__ outp) {
    extern __shared__ __align__(16) unsigned char smem_raw[];
    __half* sA  = reinterpret_cast<__half*>(smem_raw);        // [64][1032]
    __half* sxw = sA + 64 * 1032;                             // [64][32]
    float*  gsm = reinterpret_cast<float*>(sxw + 64 * 32);    // [4][64][33]
    float*  csm = gsm + 4 * 64 * 33;                          // [64][8]

    const int tid  = threadIdx.x, warp = tid >> 5, lane = tid & 31;
    const int mw   = warp & 1;          // M half: rows 32*mw..+31
    const int kh   = warp >> 1;         // K quarter (interleaved by 16 cols)
    const int cta  = blockIdx.x;
    const int c0   = cta * 32;
    const int grp  = cta >> 4;          // arrival flag group

    uint32_t bfr[16][2][4];             // phase-resident W_hh fragments

    // zero c-state (CTA-local, SMEM-resident)
    for (int i = tid; i < 64 * 8; i += 256) csm[i] = 0.f;

    for (int s = 0; s < 1024; s++) {
        const bool enc = (s < 512);
        const int  t   = enc ? s : s - 512;
        const int  e   = enc ? 0 : 1;
        const __half* __restrict__ hin  = g_h16[s & 1];
        __half*       __restrict__ hout = g_h16[(s + 1) & 1];

        // ---- prefetch xw tile (no cross-CTA dependency) ----
        {
            const __half* xwsrc = g_xw[e] + (size_t)(t * 64) * NG_ + c0;
            int b = tid >> 2, o = (tid & 3) * 8;
            cp16(sxw + b * 32 + o, xwsrc + (size_t)b * NG_ + o);
            cp_commit();
        }

        // ---- wait: all 8 group flags reached 16*s (full barrier) ----
        if (s > 0) {
            if (tid < 8) {
                const unsigned tgt = 16u * (unsigned)s;
                while (ld_acq(&g_flag[tid * 32]) < tgt) {}
            }
            __syncthreads();
        }

        // phase start: stage W_hh slice via sA, hoist B-frags into registers
        if (s == 0 || s == 512) {
            __syncthreads();   // prior compute done before sA overwrite
            const __half* src = g_whh[e] + (size_t)c0 * NH_;
            for (int i2 = tid; i2 < 32 * 128; i2 += 256) {
                int r = i2 >> 7, ch = i2 & 127;
                cp16(sA + r * 1032 + ch * 8, src + r * NH_ + ch * 8);
            }
            cp_commit();
            asm volatile("cp.async.wait_group 0;\n");   // also drains xw prefetch
            __syncthreads();
#pragma unroll
            for (int p = 0; p < 4; p++) {
#pragma unroll
                for (int i = 0; i < 4; i++) {
                    const int col = p * 256 + i * 64 + kh * 16;
#pragma unroll
                    for (int n2 = 0; n2 < 2; n2++) {
                        int nr = n2 * 16 + (lane & 7) + ((lane >> 4) << 3);
                        ldsm4(bfr[p * 4 + i][n2],
                              sA + nr * 1032 + col + ((lane >> 3) & 1) * 8);
                    }
                }
            }
            __syncthreads();   // frags in regs before sA reused for h
        }

        // ---- issue all 4 h-groups (256 cols each) at max MLP ----
#pragma unroll
        for (int g = 0; g < 4; g++) {
#pragma unroll
            for (int i = tid; i < 2048; i += 256) {
                int r = i >> 5, off = (i & 31) * 8;
                cp16(sA + r * 1032 + g * 256 + off,
                     hin + r * NH_ + g * 256 + off);
            }
            cp_commit();
        }

        float acc[2][4][4];
#pragma unroll
        for (int a = 0; a < 2; a++)
#pragma unroll
            for (int i = 0; i < 4; i++)
#pragma unroll
                for (int j = 0; j < 4; j++) acc[a][i][j] = 0.f;

        // pair P lands -> each warp does its 4 interleaved k-chunks of it
#define DO_PAIR(P, WG)                                                          \
        do {                                                                    \
            asm volatile("cp.async.wait_group %0;\n" :: "n"(WG));               \
            __syncthreads();                                                    \
            _Pragma("unroll")                                                   \
            for (int i = 0; i < 4; i++) {                                       \
                const int col = (P) * 256 + i * 64 + kh * 16;                   \
                uint32_t a[2][4];                                               \
                _Pragma("unroll")                                               \
                for (int at = 0; at < 2; at++) {                                \
                    ldsm4(a[at], sA + (mw * 32 + at * 16 + (lane & 15)) * 1032  \
                               + col + ((lane >> 4) << 3));                     \
                }                                                               \
                _Pragma("unroll")                                               \
                for (int n2 = 0; n2 < 2; n2++) {                                \
                    _Pragma("unroll")                                           \
                    for (int at = 0; at < 2; at++) {                            \
                        mma16816(acc[at][n2 * 2 + 0], a[at],                    \
                                 bfr[(P) * 4 + i][n2][0],                       \
                                 bfr[(P) * 4 + i][n2][1]);                      \
                        mma16816(acc[at][n2 * 2 + 1], a[at],                    \
                                 bfr[(P) * 4 + i][n2][2],                       \
                                 bfr[(P) * 4 + i][n2][3]);                      \
                    }                                                           \
                }                                                               \
            }                                                                   \
        } while (0)

        DO_PAIR(0, 3);
        DO_PAIR(1, 2);
        DO_PAIR(2, 1);
        DO_PAIR(3, 0);
#undef DO_PAIR

        // stage accumulators (4 K-quarter buffers) for cross-gate gather
        {
            float* gk = gsm + kh * (64 * 33);
            int r = lane >> 2;
#pragma unroll
            for (int at = 0; at < 2; at++) {
                int rb = mw * 32 + at * 16;
#pragma unroll
                for (int nt = 0; nt < 4; nt++) {
                    int ci = nt * 8 + ((lane & 3) << 1);
                    gk[(rb + r) * 33 + ci]         = acc[at][nt][0];
                    gk[(rb + r) * 33 + ci + 1]     = acc[at][nt][1];
                    gk[(rb + r + 8) * 33 + ci]     = acc[at][nt][2];
                    gk[(rb + r + 8) * 33 + ci + 1] = acc[at][nt][3];
                }
            }
        }
        __syncthreads();

        // LSTM elementwise update: 256 threads x 2 cells
        {
            int b   = tid >> 2;                     // batch row 0..63
            int jl0 = (tid & 3) * 2;                // local unit 0,2,4,6
            const float* g0 = gsm + 0 * (64 * 33) + b * 33;
            const float* g1 = gsm + 1 * (64 * 33) + b * 33;
            const float* g2b = gsm + 2 * (64 * 33) + b * 33;
            const float* g3 = gsm + 3 * (64 * 33) + b * 33;
            const __half* xr = sxw + b * 32;
            float m = enc ? mask[t * 64 + b] : 1.f;
            float hn2[2];

#pragma unroll
            for (int u = 0; u < 2; u++) {
                int jl  = jl0 + u;
                int col = jl * 4;
                float gi = g0[col + 0] + g1[col + 0] + g2b[col + 0] + g3[col + 0]
                         + __half2float(xr[col + 0]);
                float gf = g0[col + 1] + g1[col + 1] + g2b[col + 1] + g3[col + 1]
                         + __half2float(xr[col + 1]);
                float gg = g0[col + 2] + g1[col + 2] + g2b[col + 2] + g3[col + 2]
                         + __half2float(xr[col + 2]);
                float go = g0[col + 3] + g1[col + 3] + g2b[col + 3] + g3[col + 3]
                         + __half2float(xr[col + 3]);

                float ii = sigmoidf_(gi);
                float ff = sigmoidf_(gf);
                float gt = tanhf_(gg);
                float oo = sigmoidf_(go);

                int   j  = c0 / 4 + jl;             // global hidden unit
                int   ci = b * 8 + jl;              // c-state index (SMEM)
                float cp = csm[ci];
                float cn = ff * cp + ii * gt;
                float hn = oo * tanhf_(cn);

                if (enc) {
                    float hp = __half2float(sA[b * 1032 + j]);  // prev h from SMEM
                    hn = hn * m + hp * (1.f - m);
                    cn = cn * m + cp * (1.f - m);
                }
                csm[ci] = cn;
                hn2[u]  = hn;
            }
            int j0 = c0 / 4 + jl0;
            *reinterpret_cast<__half2*>(hout + b * NH_ + j0) =
                __floats2half2_rn(hn2[0], hn2[1]);
            if (!enc) {
                *reinterpret_cast<float2*>(outp + (size_t)(t * 64 + b) * NH_ + j0) =
                    make_float2(hn2[0], hn2[1]);
            }
        }

        // ---- arrival: distributed release (all CTA work, incl. reads, done) ----
        __syncthreads();
        if (tid == 0 && s != 1023) {
            red_rel_add(&g_flag[grp * 32], 1u);
        }
    }
}

// ---------------------------------------------------------------------------
// Launch
// ---------------------------------------------------------------------------
extern "C" void kernel_launch(void* const* d_in, const int* in_sizes, int n_in,
                              void* d_out, int out_size) {
    (void)in_sizes; (void)n_in; (void)out_size;
    const float* input = (const float*)d_in[0];
    const float* mask  = (const float*)d_in[1];
    const float* Wih_e = (const float*)d_in[2];
    const float* Whh_e = (const float*)d_in[3];
    const float* bih_e = (const float*)d_in[4];
    const float* bhh_e = (const float*)d_in[5];
    const float* Wih_d = (const float*)d_in[6];
    const float* Whh_d = (const float*)d_in[7];
    const float* bih_d = (const float*)d_in[8];
    const float* bhh_d = (const float*)d_in[9];
    float* out = (float*)d_out;

    cudaFuncSetAttribute(k_persist, cudaFuncAttributeMaxDynamicSharedMemorySize,
                         SMEM_PERSIST);
    cudaFuncSetAttribute(k_xw_gemm, cudaFuncAttributeMaxDynamicSharedMemorySize,
                         SMEM_XW);

    // prep: fp16 conversions, gate-interleaved weight permutation, state reset
    k_convert_x<<<(TB_ * NI_) / 4 / 256, 256>>>(input);
    k_prep<<<2048, 256>>>(Wih_e, Whh_e, bih_e, bhh_e, Wih_d, Whh_d, bih_d, bhh_d);
    k_init<<<(B_ * NH_ + 255) / 256, 256>>>();

    // batched input projections (biases folded in), enc+dec in one launch
    dim3 ggrid(NG_ / 64, TB_ / 128, 2);
    k_xw_gemm<<<ggrid, 256, SMEM_XW>>>();

    // single persistent kernel: 512 encoder + 512 decoder steps
    k_persist<<<NCTA, 256, SMEM_PERSIST>>>(mask, out);
}